// round 17
// baseline (speedup 1.0000x reference)
#include <cuda_runtime.h>
#include <cuda_fp16.h>
#include <cstdint>

#define N_NODES  100000
#define N_EDGES  1600000
#define IN_CH    128
#define HID      128
#define OUT_CH   64
#define N_GRAPHS 512

static const int NB_SCAN = (N_NODES + 1023) / 1024;   // 98

// ---------------- scratch (device globals) ----------------------------------
__device__ int    g_deg[N_NODES];
__device__ int    g_incl[N_NODES];
__device__ int    g_bsum[128];
__device__ int    g_rowptr[N_NODES + 1];
__device__ int    g_rank[N_EDGES];
__device__ int    g_srcidx[N_EDGES];
__device__ float  g_dinv[N_NODES];
__device__ __half g_hs[(size_t)N_NODES * HID];     // fp16 dinv*(X@W)
__device__ __half g_h2[(size_t)N_NODES * HID];     // fp16 conv output
__device__ uint4  g_Wp1[2048];                     // frag-packed fp16 W1
__device__ uint4  g_Wp2[2048];                     // frag-packed fp16 W2

// ---------------- side stream / events (static init: in memory baseline) ----
struct ForkRes {
    cudaStream_t s2;
    cudaEvent_t  evO, evC, evG1;
    ForkRes() {
        cudaStreamCreateWithFlags(&s2, cudaStreamNonBlocking);
        cudaEventCreateWithFlags(&evO,  cudaEventDisableTiming);
        cudaEventCreateWithFlags(&evC,  cudaEventDisableTiming);
        cudaEventCreateWithFlags(&evG1, cudaEventDisableTiming);
    }
};
static ForkRes g_fork;

// ---------------- CSR build --------------------------------------------------
// 8 edges/thread: independent atomic chains overlap the ATOMG return latency.
__global__ void k_count(const int* __restrict__ ei) {
    int t = blockIdx.x * blockDim.x + threadIdx.x;
    if (t * 8 >= N_EDGES) return;
    int4 d0 = ((const int4*)(ei + N_EDGES))[2 * t];
    int4 d1 = ((const int4*)(ei + N_EDGES))[2 * t + 1];
    int4 r0, r1;
    r0.x = atomicAdd(&g_deg[d0.x], 1);
    r0.y = atomicAdd(&g_deg[d0.y], 1);
    r0.z = atomicAdd(&g_deg[d0.z], 1);
    r0.w = atomicAdd(&g_deg[d0.w], 1);
    r1.x = atomicAdd(&g_deg[d1.x], 1);
    r1.y = atomicAdd(&g_deg[d1.y], 1);
    r1.z = atomicAdd(&g_deg[d1.z], 1);
    r1.w = atomicAdd(&g_deg[d1.w], 1);
    ((int4*)g_rank)[2 * t]     = r0;
    ((int4*)g_rank)[2 * t + 1] = r1;
}

__global__ void k_scan1() {
    __shared__ int s[1024];
    int t = threadIdx.x;
    int i = blockIdx.x * 1024 + t;
    int v = (i < N_NODES) ? g_deg[i] : 0;
    s[t] = v;
    __syncthreads();
    for (int off = 1; off < 1024; off <<= 1) {
        int a = (t >= off) ? s[t - off] : 0;
        __syncthreads();
        s[t] += a;
        __syncthreads();
    }
    if (i < N_NODES) g_incl[i] = s[t];
    if (t == 1023) g_bsum[blockIdx.x] = s[1023];
}

__global__ void k_scan3(int nb) {
    __shared__ int tmp[128];
    __shared__ int soff;
    int t = threadIdx.x;
    if (t < 128) tmp[t] = (t < (int)blockIdx.x && t < nb) ? g_bsum[t] : 0;
    __syncthreads();
    if (t == 0) {
        int s = 0;
#pragma unroll
        for (int j = 0; j < 128; j++) s += tmp[j];
        soff = s;
    }
    __syncthreads();
    int i = blockIdx.x * 1024 + t;
    if (i < N_NODES) {
        int d = g_deg[i];
        g_rowptr[i] = g_incl[i] - d + soff;
        g_dinv[i]   = rsqrtf((float)(d + 1));
    }
    if (i == 0) g_rowptr[N_NODES] = N_EDGES;
}

__global__ void k_scatter(const int* __restrict__ ei) {
    int t = blockIdx.x * blockDim.x + threadIdx.x;
    if (t * 8 >= N_EDGES) return;
    int4 s0 = ((const int4*)ei)[2 * t];
    int4 s1 = ((const int4*)ei)[2 * t + 1];
    int4 d0 = ((const int4*)(ei + N_EDGES))[2 * t];
    int4 d1 = ((const int4*)(ei + N_EDGES))[2 * t + 1];
    int4 r0 = ((const int4*)g_rank)[2 * t];
    int4 r1 = ((const int4*)g_rank)[2 * t + 1];
    g_srcidx[g_rowptr[d0.x] + r0.x] = s0.x;
    g_srcidx[g_rowptr[d0.y] + r0.y] = s0.y;
    g_srcidx[g_rowptr[d0.z] + r0.z] = s0.z;
    g_srcidx[g_rowptr[d0.w] + r0.w] = s0.w;
    g_srcidx[g_rowptr[d1.x] + r1.x] = s1.x;
    g_srcidx[g_rowptr[d1.y] + r1.y] = s1.y;
    g_srcidx[g_rowptr[d1.z] + r1.z] = s1.z;
    g_srcidx[g_rowptr[d1.w] + r1.w] = s1.w;
}

// ---------------- W frag-pack (both weights in one launch) -------------------
__global__ void k_wpack2(const float* __restrict__ W1, const float* __restrict__ W2,
                         uint4* __restrict__ Wp1, uint4* __restrict__ Wp2) {
    int blk = blockIdx.x;
    const float* W = (blk < 8) ? W1 : W2;
    uint4* Wp = (blk < 8) ? Wp1 : Wp2;
    int idx = (blk & 7) * 256 + threadIdx.x;
    int lane = idx & 31;
    int np = (idx >> 5) & 7;
    int ks = idx >> 8;
    int g = lane >> 2, s2 = (lane & 3) * 2;
    int kb = ks * 16;
    int n0 = np * 16 + g;
    int n1 = n0 + 8;
    __half2 x = __floats2half2_rn(W[(kb + s2) * HID + n0], W[(kb + s2 + 1) * HID + n0]);
    __half2 y = __floats2half2_rn(W[(kb + s2 + 8) * HID + n0], W[(kb + s2 + 9) * HID + n0]);
    __half2 z = __floats2half2_rn(W[(kb + s2) * HID + n1], W[(kb + s2 + 1) * HID + n1]);
    __half2 w = __floats2half2_rn(W[(kb + s2 + 8) * HID + n1], W[(kb + s2 + 9) * HID + n1]);
    uint4 v;
    v.x = *(unsigned*)&x; v.y = *(unsigned*)&y;
    v.z = *(unsigned*)&z; v.w = *(unsigned*)&w;
    Wp[idx] = v;
}

// ---------------- tensor-core GEMM: 64 rows/CTA, split-N warps, occ-capped --
template <bool HALF_IN>
__global__ void __launch_bounds__(256, 4) k_gemm_mma(
        const void* __restrict__ Xv, const uint4* __restrict__ Wp,
        __half* __restrict__ out, int M) {
    constexpr int AS = 136;
    extern __shared__ __half sm[];
    __half* Asm = sm;                              // [64][AS]  (17408 B)
    uint4*  Bs  = (uint4*)(sm + 64 * AS);          // [2048]    (32768 B)
    int t = threadIdx.x;
    int rowBase = blockIdx.x * 64;

    if (HALF_IN) {
        const uint4* X = (const uint4*)Xv;
        for (int idx = t; idx < 64 * 16; idx += 256) {
            int r = idx >> 4, c8 = idx & 15;
            uint4 v = make_uint4(0u, 0u, 0u, 0u);
            int gr = rowBase + r;
            if (gr < M) v = X[(size_t)gr * 16 + c8];
            *(uint4*)&Asm[r * AS + c8 * 8] = v;
        }
    } else {
        const float4* X = (const float4*)Xv;
        for (int idx = t; idx < 64 * 32; idx += 256) {
            int r = idx >> 5, c4 = idx & 31;
            float4 v = make_float4(0.f, 0.f, 0.f, 0.f);
            int gr = rowBase + r;
            if (gr < M) v = X[(size_t)gr * 32 + c4];
            *(__half2*)&Asm[r * AS + c4 * 4]     = __floats2half2_rn(v.x, v.y);
            *(__half2*)&Asm[r * AS + c4 * 4 + 2] = __floats2half2_rn(v.z, v.w);
        }
    }
    for (int idx = t; idx < 2048; idx += 256) Bs[idx] = Wp[idx];
    __syncthreads();

    int w = t >> 5, lane = t & 31;
    int g = lane >> 2, s = lane & 3;
    int strip = (w >> 1) * 16;
    int npBase = (w & 1) * 4;

    float acc[8][4];
#pragma unroll
    for (int j = 0; j < 8; j++)
#pragma unroll
        for (int q = 0; q < 4; q++) acc[j][q] = 0.f;

    const __half* Arow0 = &Asm[(strip + g) * AS + s * 2];
    const __half* Arow1 = Arow0 + 8 * AS;
#pragma unroll
    for (int ks = 0; ks < 8; ks++) {
        int kb = ks * 16;
        unsigned a0 = *(const unsigned*)(Arow0 + kb);
        unsigned a1 = *(const unsigned*)(Arow1 + kb);
        unsigned a2 = *(const unsigned*)(Arow0 + kb + 8);
        unsigned a3 = *(const unsigned*)(Arow1 + kb + 8);
        const uint4* Bk = Bs + ks * 256 + npBase * 32 + lane;
#pragma unroll
        for (int np = 0; np < 4; np++) {
            uint4 b = Bk[np * 32];
            asm volatile(
                "mma.sync.aligned.m16n8k16.row.col.f32.f16.f16.f32 "
                "{%0,%1,%2,%3}, {%4,%5,%6,%7}, {%8,%9}, {%0,%1,%2,%3};"
                : "+f"(acc[2*np][0]), "+f"(acc[2*np][1]), "+f"(acc[2*np][2]), "+f"(acc[2*np][3])
                : "r"(a0), "r"(a1), "r"(a2), "r"(a3), "r"(b.x), "r"(b.y));
            asm volatile(
                "mma.sync.aligned.m16n8k16.row.col.f32.f16.f16.f32 "
                "{%0,%1,%2,%3}, {%4,%5,%6,%7}, {%8,%9}, {%0,%1,%2,%3};"
                : "+f"(acc[2*np+1][0]), "+f"(acc[2*np+1][1]), "+f"(acc[2*np+1][2]), "+f"(acc[2*np+1][3])
                : "r"(a0), "r"(a1), "r"(a2), "r"(a3), "r"(b.z), "r"(b.w));
        }
    }

    int gr0 = rowBase + strip + g;
    int gr1 = gr0 + 8;
    float dv0 = (gr0 < M) ? rsqrtf((float)(g_deg[gr0] + 1)) : 0.f;
    float dv1 = (gr1 < M) ? rsqrtf((float)(g_deg[gr1] + 1)) : 0.f;
#pragma unroll
    for (int j = 0; j < 8; j++) {
        int col = (npBase * 2 + j) * 8 + s * 2;
        if (gr0 < M)
            *(__half2*)&out[(size_t)gr0 * HID + col] =
                __floats2half2_rn(acc[j][0] * dv0, acc[j][1] * dv0);
        if (gr1 < M)
            *(__half2*)&out[(size_t)gr1 * HID + col] =
                __floats2half2_rn(acc[j][2] * dv1, acc[j][3] * dv1);
    }
}

// ---------------- aggregation: warp per node, 2 half-warps, LDG.128 ---------
__device__ __forceinline__ void acc8(float* a, uint4 u) {
    const __half2* h = (const __half2*)&u;
#pragma unroll
    for (int j = 0; j < 4; j++) {
        float2 f = __half22float2(h[j]);
        a[2 * j]     += f.x;
        a[2 * j + 1] += f.y;
    }
}

__global__ void __launch_bounds__(256) k_agg(
        const uint4* __restrict__ hs, const float* __restrict__ bias,
        uint4* __restrict__ out) {
    int warp = (blockIdx.x * blockDim.x + threadIdx.x) >> 5;
    int lane = threadIdx.x & 31;
    if (warp >= N_NODES) return;
    int hw = lane >> 4, c = lane & 15;

    float a[8] = {0.f, 0.f, 0.f, 0.f, 0.f, 0.f, 0.f, 0.f};
    if (hw == 0) acc8(a, hs[(size_t)warp * 16 + c]);   // self loop

    int s0 = g_rowptr[warp];
    int s1 = g_rowptr[warp + 1];
    int i = s0 + hw;
    for (; i + 14 < s1; i += 16) {
        int e[8];
#pragma unroll
        for (int q = 0; q < 8; q++) e[q] = g_srcidx[i + 2 * q];
        uint4 v[8];
#pragma unroll
        for (int q = 0; q < 8; q++) v[q] = hs[(size_t)e[q] * 16 + c];
#pragma unroll
        for (int q = 0; q < 8; q++) acc8(a, v[q]);
    }
    for (; i + 6 < s1; i += 8) {
        int e0 = g_srcidx[i];
        int e1 = g_srcidx[i + 2];
        int e2 = g_srcidx[i + 4];
        int e3 = g_srcidx[i + 6];
        uint4 v0 = hs[(size_t)e0 * 16 + c];
        uint4 v1 = hs[(size_t)e1 * 16 + c];
        uint4 v2 = hs[(size_t)e2 * 16 + c];
        uint4 v3 = hs[(size_t)e3 * 16 + c];
        acc8(a, v0); acc8(a, v1); acc8(a, v2); acc8(a, v3);
    }
    for (; i < s1; i += 2) acc8(a, hs[(size_t)g_srcidx[i] * 16 + c]);

#pragma unroll
    for (int q = 0; q < 8; q++) a[q] += __shfl_down_sync(0xffffffffu, a[q], 16);

    if (hw == 0) {
        float dv = g_dinv[warp];
        float4 b0 = ((const float4*)bias)[2 * c];
        float4 b1 = ((const float4*)bias)[2 * c + 1];
        __half2 h0 = __floats2half2_rn(fmaxf(fmaf(dv, a[0], b0.x), 0.f),
                                       fmaxf(fmaf(dv, a[1], b0.y), 0.f));
        __half2 h1 = __floats2half2_rn(fmaxf(fmaf(dv, a[2], b0.z), 0.f),
                                       fmaxf(fmaf(dv, a[3], b0.w), 0.f));
        __half2 h2 = __floats2half2_rn(fmaxf(fmaf(dv, a[4], b1.x), 0.f),
                                       fmaxf(fmaf(dv, a[5], b1.y), 0.f));
        __half2 h3 = __floats2half2_rn(fmaxf(fmaf(dv, a[6], b1.z), 0.f),
                                       fmaxf(fmaf(dv, a[7], b1.w), 0.f));
        uint4 o;
        o.x = *(unsigned*)&h0; o.y = *(unsigned*)&h1;
        o.z = *(unsigned*)&h2; o.w = *(unsigned*)&h3;
        out[(size_t)warp * 16 + c] = o;
    }
}

// ---------------- fused pool + MLP head (fp32 math, exact) ------------------
__global__ void __launch_bounds__(128) k_head(
        const __half* __restrict__ h, const int* __restrict__ batch,
        const float* __restrict__ W3, const float* __restrict__ b3,
        const float* __restrict__ W4, const float* __restrict__ b4,
        float* __restrict__ out) {
    __shared__ float sp[128];
    __shared__ float sm2[128];
    int g = blockIdx.x;
    int c = threadIdx.x;

    int lo = 0, hi = N_NODES;
    while (lo < hi) { int mid = (lo + hi) >> 1; if (batch[mid] < g) lo = mid + 1; else hi = mid; }
    int start = lo;
    lo = start; hi = N_NODES;
    while (lo < hi) { int mid = (lo + hi) >> 1; if (batch[mid] < g + 1) lo = mid + 1; else hi = mid; }
    int end = lo;

    float acc = 0.f;
    for (int r = start; r < end; r++) acc += __half2float(h[(size_t)r * HID + c]);
    int cnt = end - start;
    sp[c] = acc / (float)(cnt > 0 ? cnt : 1);
    __syncthreads();

    float m = 0.f;
#pragma unroll 8
    for (int k = 0; k < HID; k++) m = fmaf(sp[k], W3[k * HID + c], m);
    sm2[c] = fmaxf(m + b3[c], 0.f);
    __syncthreads();

    if (c < OUT_CH) {
        float o = 0.f;
#pragma unroll 8
        for (int k = 0; k < HID; k++) o = fmaf(sm2[k], W4[k * OUT_CH + c], o);
        out[g * OUT_CH + c] = o + b4[c];
    }
}

// ---------------- launch ------------------------------------------------------
extern "C" void kernel_launch(void* const* d_in, const int* in_sizes, int n_in,
                              void* d_out, int out_size) {
    const float* x   = (const float*)d_in[0];
    const int*   ei  = (const int*)d_in[1];
    const int*   bat = (const int*)d_in[2];
    const float* W1  = (const float*)d_in[3];
    const float* b1  = (const float*)d_in[4];
    const float* W2  = (const float*)d_in[5];
    const float* b2  = (const float*)d_in[6];
    const float* W3  = (const float*)d_in[7];
    const float* b3  = (const float*)d_in[8];
    const float* W4  = (const float*)d_in[9];
    const float* b4  = (const float*)d_in[10];
    float* out = (float*)d_out;

    __half* hs; __half* h2; int* deg; uint4* wp1; uint4* wp2;
    cudaGetSymbolAddress((void**)&hs,  g_hs);
    cudaGetSymbolAddress((void**)&h2,  g_h2);
    cudaGetSymbolAddress((void**)&deg, g_deg);
    cudaGetSymbolAddress((void**)&wp1, g_Wp1);
    cudaGetSymbolAddress((void**)&wp2, g_Wp2);

    const int SMG = 64 * 136 * 2 + 2048 * 16;   // 50176 B
    cudaFuncSetAttribute(k_gemm_mma<false>, cudaFuncAttributeMaxDynamicSharedMemorySize, SMG);
    cudaFuncSetAttribute(k_gemm_mma<true>,  cudaFuncAttributeMaxDynamicSharedMemorySize, SMG);

    const int TB = 256;
    int nbE8 = (N_EDGES / 8 + TB - 1) / TB;
    int nbAgg = (N_NODES * 32 + TB - 1) / TB;
    int nbGemm = (N_NODES + 63) / 64;    // 1563

    cudaStream_t s2 = g_fork.s2;

    // fork at origin: W frag-packing independent of everything
    cudaEventRecord(g_fork.evO, 0);
    cudaStreamWaitEvent(s2, g_fork.evO, 0);
    k_wpack2<<<16, 256, 0, s2>>>(W1, W2, wp1, wp2);

    // main: deg + ranks (concurrent with W packing)
    cudaMemsetAsync(deg, 0, N_NODES * sizeof(int));
    k_count<<<nbE8, TB>>>(ei);
    cudaEventRecord(g_fork.evC, 0);

    // side: GEMM1 (epilogue scales by rsqrt(deg+1)) while main scans+scatters
    cudaStreamWaitEvent(s2, g_fork.evC, 0);
    k_gemm_mma<false><<<nbGemm, 256, SMG, s2>>>(x, wp1, hs, N_NODES);
    cudaEventRecord(g_fork.evG1, s2);

    k_scan1<<<NB_SCAN, 1024>>>();
    k_scan3<<<NB_SCAN, 1024>>>(NB_SCAN);
    k_scatter<<<nbE8, TB>>>(ei);

    // join; serial tail (aggs are L2-BW-bound)
    cudaStreamWaitEvent(0, g_fork.evG1, 0);

    k_agg<<<nbAgg, TB>>>((const uint4*)hs, b1, (uint4*)h2);
    k_gemm_mma<true><<<nbGemm, 256, SMG>>>(h2, wp2, hs, N_NODES);
    k_agg<<<nbAgg, TB>>>((const uint4*)hs, b2, (uint4*)h2);
    k_head<<<N_GRAPHS, 128>>>(h2, bat, W3, b3, W4, b4, out);
}